// round 3
// baseline (speedup 1.0000x reference)
#include <cuda_runtime.h>
#include <cstdint>

// Problem constants
#define BATCH 4
#define NPTS  200000
#define NGRID 128            // NX = NY = NZ = 128
#define NVOX  (BATCH * NGRID * NGRID * NGRID)   // 8,388,608 voxels
#define NWORDS (NVOX / 32)                      // 262,144 uint32 per tensor

// Scratch: 2 tensors x 1 MB bitmask = 2 MB total (static device array, no alloc)
__device__ unsigned int g_mask[2][NWORDS];

// ---------------------------------------------------------------------------
// Kernel 1: zero both bitmasks (2 MB) with 16B vector stores
// ---------------------------------------------------------------------------
__global__ void zero_mask_kernel() {
    // total uint4 elements: 2 * NWORDS / 4 = 131072
    unsigned idx = blockIdx.x * blockDim.x + threadIdx.x;
    ((uint4*)g_mask)[idx] = make_uint4(0u, 0u, 0u, 0u);
}

// ---------------------------------------------------------------------------
// Kernel 2: scatter points into occupancy bitmasks.
// grid.y = tensor index t (0 = points_a, 1 = points_b)
// One thread per point.
//
// Numeric model: XLA CPU fast-math (arcp) hoists the broadcast divisor into a
// correctly-rounded reciprocal:  q = (p - 0.5*v) * (1/v).
// We reproduce that chain exactly with _rn intrinsics.
// rintf = round-half-even = jnp.round.
// ---------------------------------------------------------------------------
__device__ __forceinline__ int voxel_coord(float p, float v, float rinv) {
    float half    = __fmul_rn(v, 0.5f);        // exact
    float shifted = __fsub_rn(p, half);        // IEEE sub
    float q       = __fmul_rn(shifted, rinv);  // multiply by CR reciprocal (arcp)
    return (int)rintf(q) + 64;
}

__global__ void scatter_kernel(const float* __restrict__ pts_a,
                               const float* __restrict__ pts_b,
                               const float* __restrict__ vs) {
    unsigned idx = blockIdx.x * blockDim.x + threadIdx.x;  // over BATCH*NPTS
    if (idx >= BATCH * NPTS) return;
    const int t = blockIdx.y;
    const float* __restrict__ pts = (t == 0) ? pts_a : pts_b;

    const int b = idx / NPTS;
    const float vx = __ldg(&vs[b * 3 + 0]);
    const float vy = __ldg(&vs[b * 3 + 1]);
    const float vz = __ldg(&vs[b * 3 + 2]);

    // correctly-rounded reciprocals (IEEE divide; NOT MUFU.RCP)
    const float rx = __fdiv_rn(1.0f, vx);
    const float ry = __fdiv_rn(1.0f, vy);
    const float rz = __fdiv_rn(1.0f, vz);

    const float px = pts[(size_t)idx * 3 + 0];
    const float py = pts[(size_t)idx * 3 + 1];
    const float pz = pts[(size_t)idx * 3 + 2];

    const int i = voxel_coord(px, vx, rx);
    const int j = voxel_coord(py, vy, ry);
    const int k = voxel_coord(pz, vz, rz);

    if ((unsigned)i < NGRID && (unsigned)j < NGRID && (unsigned)k < NGRID) {
        const unsigned lin = (((unsigned)b * NGRID + i) * NGRID + j) * NGRID + k;
        atomicOr(&g_mask[t][lin >> 5], 1u << (lin & 31u));
    }
}

// ---------------------------------------------------------------------------
// Kernel 3: expand bitmasks into the output tensor.
// out layout: [B, 128, 128, 128, 4] f32 -> one float4 per voxel.
//   c=0,1: occ_a * emb[0][0..1];  c=2,3: occ_b * emb[1][0..1]
// ---------------------------------------------------------------------------
__global__ void expand_kernel(float4* __restrict__ out,
                              const float* __restrict__ emb) {
    const unsigned lin = blockIdx.x * blockDim.x + threadIdx.x;  // < NVOX
    const unsigned w   = lin >> 5;
    const unsigned bit = lin & 31u;

    const unsigned wa = g_mask[0][w];
    const unsigned wb = g_mask[1][w];

    const float e00 = __ldg(&emb[0]);
    const float e01 = __ldg(&emb[1]);
    const float e10 = __ldg(&emb[2]);
    const float e11 = __ldg(&emb[3]);

    const bool a = (wa >> bit) & 1u;
    const bool c = (wb >> bit) & 1u;

    out[lin] = make_float4(a ? e00 : 0.0f,
                           a ? e01 : 0.0f,
                           c ? e10 : 0.0f,
                           c ? e11 : 0.0f);
}

// ---------------------------------------------------------------------------
// Launch
// Inputs (metadata order): points_a [4,200000,3] f32, points_b [4,200000,3] f32,
//                          neck_voxel_sizes [4,3] f32, embedding_weight [2,2] f32
// Output: [4,128,128,128,4] f32  (33,554,432 floats)
// ---------------------------------------------------------------------------
extern "C" void kernel_launch(void* const* d_in, const int* in_sizes, int n_in,
                              void* d_out, int out_size) {
    const float* pts_a = (const float*)d_in[0];
    const float* pts_b = (const float*)d_in[1];
    const float* vs    = (const float*)d_in[2];
    const float* emb   = (const float*)d_in[3];
    float4* out        = (float4*)d_out;

    // 1) zero bitmasks: 2*NWORDS/4 = 131072 uint4
    zero_mask_kernel<<<131072 / 256, 256>>>();

    // 2) scatter both point sets
    dim3 sgrid((BATCH * NPTS + 255) / 256, 2);
    scatter_kernel<<<sgrid, 256>>>(pts_a, pts_b, vs);

    // 3) expand to output: NVOX float4 writes
    expand_kernel<<<NVOX / 256, 256>>>(out, emb);
}